// round 14
// baseline (speedup 1.0000x reference)
#include <cuda_runtime.h>
#include <cuda_fp16.h>
#include <cstdint>

// ---------------------------------------------------------------------------
// Problem dims (fixed)
// ---------------------------------------------------------------------------
#define Bsz 8192
#define Tsz 20
#define Hsz 256
#define Psz 15
#define NG  1024   // 4*H gates (packed col order: 4*unit + gate)

// ---------------------------------------------------------------------------
// Static device scratch
// ---------------------------------------------------------------------------
__device__ __half g_h1[(size_t)Tsz * Bsz * 64];      // relu(x@Wi+b) fp16
__device__ __half g_h[2][(size_t)Bsz * 256];         // h state fp16
__device__ float  g_c[(size_t)Bsz * Hsz];            // c state fp32
__device__ __half g_D0h[(size_t)Bsz * NG];           // enc_h @ dec_k, fp16 (packed cols)
__device__ float  g_dec[(size_t)Bsz * Psz * Hsz];    // decoder h outputs fp32
__device__ __half g_We [320 * NG];                   // [enc_k;enc_rk] fp16, packed cols
__device__ __half g_Wdr[256 * NG];                   // dec_rk fp16
__device__ __half g_Wdi[256 * NG];                   // dec_k  fp16
__device__ float  g_bias_e[NG];                      // permuted enc_b
__device__ float  g_bias_d[NG];                      // permuted dec_b
__device__ int    g_cnt[64];                         // per-row-block h-write counter

// ---------------------------------------------------------------------------
// Activation helpers
// ---------------------------------------------------------------------------
__device__ __forceinline__ float sigm_(float x) { return 1.f / (1.f + __expf(-x)); }
__device__ __forceinline__ float tanh_(float x) {
    float e = __expf(-2.f * fabsf(x));
    float t = (1.f - e) / (1.f + e);
    return copysignf(t, x);
}

// ---------------------------------------------------------------------------
// Weight packing (gate-interleaved columns: packed col n' = 4u+g <- g*256+u)
// ---------------------------------------------------------------------------
__global__ void k_pack_enc(const float* __restrict__ ek, const float* __restrict__ erk) {
    int idx = blockIdx.x * blockDim.x + threadIdx.x;
    if (idx >= 320 * NG) return;
    int r = idx >> 10, np = idx & 1023;
    int u = np >> 2, gg = np & 3, nc = gg * 256 + u;
    float w = (r < 64) ? ek[r * NG + nc] : erk[(r - 64) * NG + nc];
    g_We[idx] = __float2half_rn(w);
}

__global__ void k_pack_256(const float* __restrict__ w, int sel) {
    int idx = blockIdx.x * blockDim.x + threadIdx.x;
    if (idx >= 256 * NG) return;
    int np = idx & 1023;
    int u = np >> 2, gg = np & 3, nc = gg * 256 + u;
    int r = idx >> 10;
    __half* dst = sel ? g_Wdi : g_Wdr;
    dst[idx] = __float2half_rn(w[r * NG + nc]);
}

__global__ void k_pack_bias(const float* __restrict__ eb, const float* __restrict__ db) {
    int idx = blockIdx.x * blockDim.x + threadIdx.x;
    if (idx >= 2048) return;
    int np = idx & 1023;
    int u = np >> 2, gg = np & 3;
    if (idx < 1024) g_bias_e[np] = eb[gg * 256 + u];
    else            g_bias_d[np] = db[gg * 256 + u];
}

__global__ void k_zero_cnt() {
    if (threadIdx.x < 64) g_cnt[threadIdx.x] = 0;
}

// ---------------------------------------------------------------------------
// Input projection: h1 = relu(x @ w_in_k + w_in_b) -> fp16; 32 rows/block
// ---------------------------------------------------------------------------
__global__ void k_inproj(const float* __restrict__ x, const float* __restrict__ wk,
                         const float* __restrict__ wb) {
    __shared__ float ws[512];
    __shared__ float xs[32][8];
    __shared__ float bsh[64];
    int tid = threadIdx.x;                       // 256 threads
    ws[tid] = wk[tid];
    ws[tid + 256] = wk[tid + 256];
    if (tid < 64) bsh[tid] = wb[tid];
    int rowbase = blockIdx.x * 32;
    xs[tid >> 3][tid & 7] = x[(size_t)(rowbase + (tid >> 3)) * 8 + (tid & 7)];
    __syncthreads();
    int n = tid & 63, rg = tid >> 6;
#pragma unroll
    for (int r = 0; r < 8; r++) {
        int row = rowbase + rg * 8 + r;
        float acc = bsh[n];
#pragma unroll
        for (int k = 0; k < 8; k++) acc = fmaf(xs[rg * 8 + r][k], ws[k * 64 + n], acc);
        acc = fmaxf(acc, 0.f);
        int b = row / 20, t2 = row - b * 20;
        g_h1[((size_t)t2 * Bsz + b) * 64 + n] = __float2half_rn(acc);
    }
}

// ---------------------------------------------------------------------------
// Persistent fused LSTM kernel: 36 phases, 296 CTAs (2/SM), fixed tile map.
//   phase 0      : enc step0 (mode2, KT=2, h1 only)
//   phase 1..19  : enc steps (mode0, KT=10)
//   phase 20     : D0 = enc_h @ dec_k (mode1, epi0)
//   phase 21     : dec step0 pointwise (mode3)
//   phase 22..35 : dec steps (mode1, epi2)
// ---------------------------------------------------------------------------
#define BM   128
#define BN   128
#define ASTR 40
#define BSTR 136
#define ASTAGE (BM * ASTR * 2)            // 10240 B
#define BSTAGE (32 * BSTR * 2)            // 8704 B
#define SMA(st) ((st) * ASTAGE)
#define SMB(st) (3 * ASTAGE + (st) * BSTAGE)
#define SMEM3 (3 * ASTAGE + 3 * BSTAGE)   // 56832 B
#define CSTR 36
#define HSTR 72
#define NCTA 296

__global__ void __launch_bounds__(256, 2) k_persist() {
    extern __shared__ __align__(16) char smem[];
    const int tid = threadIdx.x, lane = tid & 31, warp = tid >> 5;
    const int cta = blockIdx.x;
    const int wm = (warp >> 1) * 32;
    const int wn = (warp & 1) * 64;
    const int odd = lane & 1;

    int hwrites = 0;
    for (int s = 0; s < 36; s++) {
        // ---- step descriptor ----
        int mode, wsel, epi, tstep, czero, pstep, bsel, rdbuf, wrbuf, needh, bumps;
        if (s == 0) {
            mode = 2; wsel = 0; epi = 1; tstep = 0; czero = 1; pstep = -1;
            bsel = 0; rdbuf = 0; wrbuf = 1; needh = 0; bumps = 1;
        } else if (s < 20) {
            mode = 0; wsel = 0; epi = 1; tstep = s; czero = 0; pstep = -1;
            bsel = 0; rdbuf = s & 1; wrbuf = (s + 1) & 1; needh = 1; bumps = 1;
        } else if (s == 20) {
            mode = 1; wsel = 2; epi = 0; tstep = -1; czero = 0; pstep = -1;
            bsel = 1; rdbuf = 0; wrbuf = 0; needh = 1; bumps = 0;
        } else {
            int d = s - 21;
            if (d == 0) {
                mode = 3; wsel = 0; epi = 2; tstep = -1; czero = 1; pstep = 0;
                bsel = 1; rdbuf = 0; wrbuf = 1; needh = 0; bumps = 1;
            } else {
                mode = 1; wsel = 1; epi = 2; tstep = -1; czero = 0; pstep = d;
                bsel = 1; rdbuf = d & 1; wrbuf = (d + 1) & 1; needh = 1; bumps = 1;
            }
        }
        const int target = 8 * hwrites;
        const int KT = (mode == 0) ? 10 : (mode == 1) ? 8 : 2;

        for (int ti = 0; ti < 2; ti++) {
            int T = cta + ti * NCTA;
            if (T >= 512) break;
            const int mb = T & 63, nb = T >> 6;
            const int mblk = mb * BM, nblk = nb * BN;

            // ================= dec step 0: pointwise =================
            if (mode == 3) {
                for (int idx = tid; idx < 4096; idx += 256) {
                    int row = idx >> 5, u = idx & 31;
                    size_t rg = (size_t)(mblk + row) * NG + nblk + 4 * u;
                    __half2 z01 = *(const __half2*)&g_D0h[rg];
                    __half2 z23 = *(const __half2*)&g_D0h[rg + 2];
                    float4 bi = *(const float4*)&g_bias_d[nblk + 4 * u];
                    float i = sigm_(__half2float(z01.x) + bi.x);
                    float g = tanh_(__half2float(z23.x) + bi.z);
                    float o = sigm_(__half2float(z23.y) + bi.w);
                    float cn = i * g;                       // c_old = 0
                    int uu = (nblk >> 2) + u;
                    g_c[(size_t)(mblk + row) * Hsz + uu] = cn;
                    float h = o * tanh_(cn);
                    g_h[1][(size_t)(mblk + row) * 256 + uu] = __float2half_rn(h);
                    g_dec[((size_t)(mblk + row) * Psz + 0) * Hsz + uu] = h;
                }
                __threadfence();
                __syncthreads();
                if (tid == 0) atomicAdd(&g_cnt[mb], 1);
                continue;
            }

            // ================= GEMM tile =================
            const __half* __restrict__ Ah  = g_h[rdbuf];
            const __half* __restrict__ Ah1 = g_h1 + (size_t)((tstep < 0) ? 0 : tstep) * Bsz * 64;
            const __half* __restrict__ Bw  = (wsel == 0) ? g_We : (wsel == 1) ? g_Wdr : g_Wdi;

            float acc[2][8][4];
#pragma unroll
            for (int a = 0; a < 2; a++)
#pragma unroll
                for (int b = 0; b < 8; b++)
#pragma unroll
                    for (int c = 0; c < 4; c++) acc[a][b][c] = 0.f;

            auto loadTile = [&](int kt, int st) {
                const __half* src; int stride, col;
                int brow = kt * 32;
                if (mode == 0) {
                    if (kt < 2) { src = Ah1; stride = 64;  col = kt * 32; }
                    else        { src = Ah;  stride = 256; col = (kt - 2) * 32; }
                } else if (mode == 1) {
                    src = Ah; stride = 256; col = kt * 32;
                } else {
                    src = Ah1; stride = 64; col = kt * 32;
                }
                __half* dA = (__half*)(smem + SMA(st));
#pragma unroll
                for (int j = 0; j < 2; j++) {
                    int ci = tid + j * 256;
                    int row = ci >> 2, c16 = ci & 3;
                    const __half* g = src + (size_t)(mblk + row) * stride + col + c16 * 8;
                    uint32_t sa = (uint32_t)__cvta_generic_to_shared(dA + row * ASTR + c16 * 8);
                    asm volatile("cp.async.cg.shared.global [%0], [%1], 16;\n" :: "r"(sa), "l"(g));
                }
                __half* dB = (__half*)(smem + SMB(st));
#pragma unroll
                for (int j = 0; j < 2; j++) {
                    int ci = tid + j * 256;
                    int row = ci >> 4, c16 = ci & 15;
                    const __half* g = Bw + (size_t)(brow + row) * NG + nblk + c16 * 8;
                    uint32_t sb = (uint32_t)__cvta_generic_to_shared(dB + row * BSTR + c16 * 8);
                    asm volatile("cp.async.cg.shared.global [%0], [%1], 16;\n" :: "r"(sb), "l"(g));
                }
                asm volatile("cp.async.commit_group;\n");
            };

            // dependency wait (encoder can prefetch h1 k-tiles first)
            if (mode == 0) {
                loadTile(0, 0);
                loadTile(1, 1);
                if (needh) {
                    if (tid == 0) { while (((volatile int*)g_cnt)[mb] < target) {} }
                    __syncthreads();
                    __threadfence();
                }
            } else {
                if (needh) {
                    if (tid == 0) { while (((volatile int*)g_cnt)[mb] < target) {} }
                    __syncthreads();
                    __threadfence();
                }
                loadTile(0, 0);
                loadTile(1, 1);
            }

            for (int kt = 0; kt < KT; kt++) {
                int st = kt % 3;
                if (kt + 1 < KT) { asm volatile("cp.async.wait_group 1;\n"); }
                else             { asm volatile("cp.async.wait_group 0;\n"); }
                __syncthreads();
                if (kt + 2 < KT) loadTile(kt + 2, (kt + 2) % 3);
                const __half* cA = (const __half*)(smem + SMA(st));
                const __half* cB = (const __half*)(smem + SMB(st));
#pragma unroll
                for (int ks = 0; ks < 2; ks++) {
                    uint32_t a[2][4], bf[4][4];
#pragma unroll
                    for (int mf = 0; mf < 2; mf++) {
                        uint32_t ad = (uint32_t)__cvta_generic_to_shared(
                            cA + (wm + mf * 16 + (lane & 15)) * ASTR + ks * 16 + (lane >> 4) * 8);
                        asm volatile("ldmatrix.sync.aligned.x4.m8n8.shared.b16 {%0,%1,%2,%3}, [%4];\n"
                                     : "=r"(a[mf][0]), "=r"(a[mf][1]), "=r"(a[mf][2]), "=r"(a[mf][3])
                                     : "r"(ad));
                    }
#pragma unroll
                    for (int ng = 0; ng < 4; ng++) {
                        uint32_t ad = (uint32_t)__cvta_generic_to_shared(
                            cB + (ks * 16 + ((lane >> 3) & 1) * 8 + (lane & 7)) * BSTR
                               + wn + ng * 16 + (lane >> 4) * 8);
                        asm volatile("ldmatrix.sync.aligned.x4.trans.m8n8.shared.b16 {%0,%1,%2,%3}, [%4];\n"
                                     : "=r"(bf[ng][0]), "=r"(bf[ng][1]), "=r"(bf[ng][2]), "=r"(bf[ng][3])
                                     : "r"(ad));
                    }
#pragma unroll
                    for (int mf = 0; mf < 2; mf++)
#pragma unroll
                        for (int j = 0; j < 8; j++) {
                            uint32_t b0 = bf[j >> 1][(j & 1) * 2], b1 = bf[j >> 1][(j & 1) * 2 + 1];
                            asm volatile(
                                "mma.sync.aligned.m16n8k16.row.col.f32.f16.f16.f32 "
                                "{%0,%1,%2,%3}, {%4,%5,%6,%7}, {%8,%9}, {%0,%1,%2,%3};\n"
                                : "+f"(acc[mf][j][0]), "+f"(acc[mf][j][1]),
                                  "+f"(acc[mf][j][2]), "+f"(acc[mf][j][3])
                                : "r"(a[mf][0]), "r"(a[mf][1]), "r"(a[mf][2]), "r"(a[mf][3]),
                                  "r"(b0), "r"(b1));
                        }
                }
            }

            // ---------------- Epilogue ----------------
            if (epi == 0) {   // raw z -> g_D0h fp16 (CTA-private block)
#pragma unroll
                for (int mf = 0; mf < 2; mf++) {
                    int r0 = mblk + wm + mf * 16 + (lane >> 2);
#pragma unroll
                    for (int j = 0; j < 8; j++) {
                        int n = nblk + wn + j * 8 + (lane & 3) * 2;
                        *(__half2*)&g_D0h[(size_t)r0 * NG + n] =
                            __floats2half2_rn(acc[mf][j][0], acc[mf][j][1]);
                        *(__half2*)&g_D0h[(size_t)(r0 + 8) * NG + n] =
                            __floats2half2_rn(acc[mf][j][2], acc[mf][j][3]);
                    }
                }
                __syncthreads();   // smem reuse safety for next tile
                continue;
            }

            float*  cS = (float*)smem;
            __half* hS = (__half*)(smem + 128 * CSTR * 4);
            const int u0 = nblk >> 2;

            __syncthreads();
            if (!czero) {
#pragma unroll
                for (int i = tid; i < 1024; i += 256) {
                    int row = i >> 3, c4 = i & 7;
                    float4 v = *(const float4*)&g_c[(size_t)(mblk + row) * Hsz + u0 + c4 * 4];
                    *(float4*)&cS[row * CSTR + c4 * 4] = v;
                }
            }
            __syncthreads();

            const float* __restrict__ bp = bsel ? g_bias_d : g_bias_e;
#pragma unroll
            for (int mf = 0; mf < 2; mf++) {
                int r0 = mblk + wm + mf * 16 + (lane >> 2);
#pragma unroll
                for (int j = 0; j < 8; j++) {
                    int n = nblk + wn + j * 8 + (lane & 3) * 2;
                    float c0 = acc[mf][j][0], c1 = acc[mf][j][1];
                    float c2 = acc[mf][j][2], c3 = acc[mf][j][3];
                    float2 bb = *(const float2*)&bp[n];
                    c0 += bb.x; c1 += bb.y; c2 += bb.x; c3 += bb.y;
                    if (epi == 2) {
                        float2 dA = __half22float2(*(const __half2*)&g_D0h[(size_t)r0 * NG + n]);
                        float2 dB = __half22float2(*(const __half2*)&g_D0h[(size_t)(r0 + 8) * NG + n]);
                        c0 += dA.x; c1 += dA.y; c2 += dB.x; c3 += dB.y;
                    }
                    float p0 = __shfl_xor_sync(0xFFFFFFFFu, c0, 1);
                    float p1 = __shfl_xor_sync(0xFFFFFFFFu, c1, 1);
                    float p2 = __shfl_xor_sync(0xFFFFFFFFu, c2, 1);
                    float p3 = __shfl_xor_sync(0xFFFFFFFFu, c3, 1);
                    float gi = odd ? p2 : c0;
                    float gf = odd ? p3 : c1;
                    float gg = odd ? c2 : p0;
                    float go = odd ? c3 : p1;
                    int rloc = wm + mf * 16 + (lane >> 2) + (odd ? 8 : 0);
                    int uloc = ((wn + j * 8) >> 2) + ((lane >> 1) & 1);
                    float i = sigm_(gi), f = sigm_(gf), g = tanh_(gg), o = sigm_(go);
                    float cold = czero ? 0.f : cS[rloc * CSTR + uloc];
                    float cn = f * cold + i * g;
                    float h = o * tanh_(cn);
                    cS[rloc * CSTR + uloc] = cn;
                    __half hh = __float2half_rn(h);
                    hS[rloc * HSTR + uloc] = hh;
                    if (epi == 2)
                        hS[rloc * HSTR + 32 + uloc] = __float2half_rn(h - __half2float(hh));
                }
            }
            __syncthreads();

            __half* __restrict__ hd = g_h[wrbuf];
#pragma unroll
            for (int i = tid; i < 1024; i += 256) {
                int row = i >> 3, c4 = i & 7;
                float4 v = *(const float4*)&cS[row * CSTR + c4 * 4];
                *(float4*)&g_c[(size_t)(mblk + row) * Hsz + u0 + c4 * 4] = v;
            }
#pragma unroll
            for (int i = tid; i < 512; i += 256) {
                int row = i >> 2, c16 = i & 3;
                uint4 v = *(const uint4*)&hS[row * HSTR + c16 * 8];
                *(uint4*)&hd[(size_t)(mblk + row) * 256 + u0 + c16 * 8] = v;
            }
            if (epi == 2) {
#pragma unroll
                for (int i = tid; i < 1024; i += 256) {
                    int row = i >> 3, c4 = i & 7;
                    const __half* hp = &hS[row * HSTR + c4 * 4];
                    float4 o;
                    o.x = __half2float(hp[0]) + __half2float(hp[32]);
                    o.y = __half2float(hp[1]) + __half2float(hp[33]);
                    o.z = __half2float(hp[2]) + __half2float(hp[34]);
                    o.w = __half2float(hp[3]) + __half2float(hp[35]);
                    *(float4*)&g_dec[((size_t)(mblk + row) * Psz + pstep) * Hsz + u0 + c4 * 4] = o;
                }
            }
            // publish h-write for this (m,·) tile
            __threadfence();
            __syncthreads();
            if (tid == 0) atomicAdd(&g_cnt[mb], 1);
        }
        hwrites += bumps;
    }
}

// ---------------------------------------------------------------------------
// Output heads
// ---------------------------------------------------------------------------
__global__ void k_heads(const float* __restrict__ mk, const float* __restrict__ mb,
                        const float* __restrict__ lk, const float* __restrict__ lb,
                        float* __restrict__ out) {
    int gw = (blockIdx.x * blockDim.x + threadIdx.x) >> 5;
    int lane = threadIdx.x & 31;
    if (gw >= Bsz * Psz) return;
    const float4* d4 = (const float4*)(g_dec + (size_t)gw * Hsz) + lane * 2;
    float4 va = d4[0], vb = d4[1];
    float dv[8] = {va.x, va.y, va.z, va.w, vb.x, vb.y, vb.z, vb.w};
    float m0 = 0.f, m1 = 0.f, v0 = 0.f, v1 = 0.f;
#pragma unroll
    for (int i = 0; i < 8; i++) {
        int k = lane * 8 + i;
        m0 = fmaf(dv[i], mk[2 * k],     m0);
        m1 = fmaf(dv[i], mk[2 * k + 1], m1);
        v0 = fmaf(dv[i], lk[2 * k],     v0);
        v1 = fmaf(dv[i], lk[2 * k + 1], v1);
    }
#pragma unroll
    for (int off = 16; off; off >>= 1) {
        m0 += __shfl_xor_sync(0xFFFFFFFFu, m0, off);
        m1 += __shfl_xor_sync(0xFFFFFFFFu, m1, off);
        v0 += __shfl_xor_sync(0xFFFFFFFFu, v0, off);
        v1 += __shfl_xor_sync(0xFFFFFFFFu, v1, off);
    }
    if (lane == 0) {
        float4 r = make_float4(m0 + mb[0], m1 + mb[1],
                               fmaxf(v0 + lb[0], 0.f), fmaxf(v1 + lb[1], 0.f));
        *(float4*)&out[(size_t)gw * 4] = r;
    }
}

// ---------------------------------------------------------------------------
// Launch
// ---------------------------------------------------------------------------
extern "C" void kernel_launch(void* const* d_in, const int* in_sizes, int n_in,
                              void* d_out, int out_size) {
    (void)in_sizes; (void)n_in; (void)out_size;
    const float* x      = (const float*)d_in[0];
    const float* w_in_k = (const float*)d_in[1];
    const float* w_in_b = (const float*)d_in[2];
    const float* enc_k  = (const float*)d_in[3];
    const float* enc_rk = (const float*)d_in[4];
    const float* enc_b  = (const float*)d_in[5];
    const float* dec_k  = (const float*)d_in[6];
    const float* dec_rk = (const float*)d_in[7];
    const float* dec_b  = (const float*)d_in[8];
    const float* mean_k = (const float*)d_in[9];
    const float* mean_b = (const float*)d_in[10];
    const float* lv_k   = (const float*)d_in[11];
    const float* lv_b   = (const float*)d_in[12];
    float* out = (float*)d_out;

    cudaFuncSetAttribute(k_persist, cudaFuncAttributeMaxDynamicSharedMemorySize, SMEM3);

    k_pack_enc<<<(320 * NG + 255) / 256, 256>>>(enc_k, enc_rk);
    k_pack_256<<<(256 * NG + 255) / 256, 256>>>(dec_rk, 0);
    k_pack_256<<<(256 * NG + 255) / 256, 256>>>(dec_k, 1);
    k_pack_bias<<<8, 256>>>(enc_b, dec_b);
    k_inproj<<<(Bsz * Tsz) / 32, 256>>>(x, w_in_k, w_in_b);
    k_zero_cnt<<<1, 64>>>();

    k_persist<<<NCTA, 256, SMEM3>>>();

    k_heads<<<(Bsz * Psz * 32 + 255) / 256, 256>>>(mean_k, mean_b, lv_k, lv_b, out);
}

// round 16
// speedup vs baseline: 1.2733x; 1.2733x over previous
#include <cuda_runtime.h>
#include <cuda_fp16.h>
#include <cstdint>

// ---------------------------------------------------------------------------
// Problem dims (fixed)
// ---------------------------------------------------------------------------
#define Bsz 8192
#define Tsz 20
#define Hsz 256
#define Psz 15
#define NG  1024   // 4*H gates (packed col order: 4*unit + gate)

// ---------------------------------------------------------------------------
// Static device scratch
// ---------------------------------------------------------------------------
__device__ __half g_h1[(size_t)Tsz * Bsz * 64];      // relu(x@Wi+b) fp16
__device__ __half g_h[2][(size_t)Bsz * 256];         // h state fp16
__device__ float  g_c[(size_t)Bsz * Hsz];            // c state fp32
__device__ __half g_D0h[(size_t)Bsz * NG];           // enc_h @ dec_k, fp16 (packed cols)
__device__ float  g_dec[(size_t)Bsz * Psz * Hsz];    // decoder h outputs fp32
__device__ __half g_We [320 * NG];                   // [enc_k;enc_rk] fp16 [k][np]
__device__ __half g_Wdr[256 * NG];                   // dec_rk fp16 [k][np]
__device__ __half g_Wdi[256 * NG];                   // dec_k  fp16 [k][np]
__device__ float  g_bias_e[NG];
__device__ float  g_bias_d[NG];

// ---------------------------------------------------------------------------
// Activation helpers
// ---------------------------------------------------------------------------
__device__ __forceinline__ float sigm_(float x) { return 1.f / (1.f + __expf(-x)); }
__device__ __forceinline__ float tanh_(float x) {
    float e = __expf(-2.f * fabsf(x));
    float t = (1.f - e) / (1.f + e);
    return copysignf(t, x);
}

// ---------------------------------------------------------------------------
// All weight/bias packing in ONE kernel (keeps ncu -s 5 on a GEMM launch).
// packed col np = 4u+g <- nc = g*256+u
// ---------------------------------------------------------------------------
__global__ void k_pack_all(const float* __restrict__ ek, const float* __restrict__ erk,
                           const float* __restrict__ drk, const float* __restrict__ dk,
                           const float* __restrict__ eb, const float* __restrict__ db) {
    int idx = blockIdx.x * blockDim.x + threadIdx.x;
    if (idx < 320 * NG) {
        int r = idx >> 10, np = idx & 1023;
        int u = np >> 2, gg = np & 3, nc = gg * 256 + u;
        float w = (r < 64) ? ek[r * NG + nc] : erk[(r - 64) * NG + nc];
        g_We[idx] = __float2half_rn(w);
    } else if (idx < 576 * NG) {
        int j = idx - 320 * NG;
        int r = j >> 10, np = j & 1023;
        int u = np >> 2, gg = np & 3, nc = gg * 256 + u;
        g_Wdr[j] = __float2half_rn(drk[r * NG + nc]);
    } else if (idx < 832 * NG) {
        int j = idx - 576 * NG;
        int r = j >> 10, np = j & 1023;
        int u = np >> 2, gg = np & 3, nc = gg * 256 + u;
        g_Wdi[j] = __float2half_rn(dk[r * NG + nc]);
    } else if (idx < 832 * NG + 2048) {
        int j = idx - 832 * NG;
        int np = j & 1023;
        int u = np >> 2, gg = np & 3;
        if (j < 1024) g_bias_e[np] = eb[gg * 256 + u];
        else          g_bias_d[np] = db[gg * 256 + u];
    }
}

// ---------------------------------------------------------------------------
// Input projection: h1 = relu(x @ w_in_k + w_in_b) -> fp16; 32 rows/block
// ---------------------------------------------------------------------------
__global__ void k_inproj(const float* __restrict__ x, const float* __restrict__ wk,
                         const float* __restrict__ wb) {
    __shared__ float ws[512];
    __shared__ float xs[32][8];
    __shared__ float bsh[64];
    int tid = threadIdx.x;                       // 256 threads
    ws[tid] = wk[tid];
    ws[tid + 256] = wk[tid + 256];
    if (tid < 64) bsh[tid] = wb[tid];
    int rowbase = blockIdx.x * 32;
    xs[tid >> 3][tid & 7] = x[(size_t)(rowbase + (tid >> 3)) * 8 + (tid & 7)];
    __syncthreads();
    int n = tid & 63, rg = tid >> 6;
#pragma unroll
    for (int r = 0; r < 8; r++) {
        int row = rowbase + rg * 8 + r;
        float acc = bsh[n];
#pragma unroll
        for (int k = 0; k < 8; k++) acc = fmaf(xs[rg * 8 + r][k], ws[k * 64 + n], acc);
        acc = fmaxf(acc, 0.f);
        int b = row / 20, t2 = row - b * 20;
        g_h1[((size_t)t2 * Bsz + b) * 64 + n] = __float2half_rn(acc);
    }
}

// ---------------------------------------------------------------------------
// Fused GEMM + LSTM cell. BM=64 BN=128, 256 thr, 2-stage, 4 CTAs/SM.
//   mode: 0 = encoder (KT=10, K=320), 1 = decoder (KT=8, K=256),
//         2 = enc step0 (KT=2, K=64, h1 only)
//   epi:  0 = raw z -> g_D0h fp16, 1 = enc cell, 2 = dec cell (+D0, g_dec)
// ---------------------------------------------------------------------------
#define BM   64
#define BN   128
#define ASTR 40
#define BSTR 136
#define ASTAGE (BM * ASTR * 2)            // 5120 B
#define BSTAGE (32 * BSTR * 2)            // 8704 B
#define SMEMT  (2 * (ASTAGE + BSTAGE))    // 27648 B
#define CSTR 36
#define HSTR 72

__global__ void __launch_bounds__(256, 4) k_gemm(
    int mode, int wsel, int epi, int abuf, int tstep,
    int dstbuf, int czero, int pstep, int bsel)
{
    __shared__ __align__(16) char smem[SMEMT];

    const int KT = (mode == 0) ? 10 : (mode == 1) ? 8 : 2;
    const __half* __restrict__ Ah  = g_h[abuf];
    const __half* __restrict__ Ah1 = g_h1 + (size_t)((tstep < 0) ? 0 : tstep) * Bsz * 64;
    const __half* __restrict__ Bw  = (wsel == 0) ? g_We : (wsel == 1) ? g_Wdr : g_Wdi;

    const int tid = threadIdx.x, lane = tid & 31, warp = tid >> 5;
    const int mblk = blockIdx.x * BM;   // gridDim.x = 128
    const int nblk = blockIdx.y * BN;   // gridDim.y = 8
    const int wm = (warp >> 2) * 32;    // 2 M groups
    const int wn = (warp & 3) * 32;     // 4 N groups

    float acc[2][4][4];
#pragma unroll
    for (int a = 0; a < 2; a++)
#pragma unroll
        for (int b = 0; b < 4; b++)
#pragma unroll
            for (int c = 0; c < 4; c++) acc[a][b][c] = 0.f;

    auto loadTile = [&](int kt, int s) {
        const __half* src; int stride, col;
        int brow = kt * 32;
        if (mode == 0) {
            if (kt < 2) { src = Ah1; stride = 64;  col = kt * 32; }
            else        { src = Ah;  stride = 256; col = (kt - 2) * 32; }
        } else if (mode == 1) {
            src = Ah; stride = 256; col = kt * 32;
        } else {
            src = Ah1; stride = 64; col = kt * 32;
        }
        __half* dA = (__half*)(smem + s * ASTAGE);
        {   // A: 256 chunks of 16B, 1 per thread
            int row = tid >> 2, c16 = tid & 3;
            const __half* g = src + (size_t)(mblk + row) * stride + col + c16 * 8;
            uint32_t sa = (uint32_t)__cvta_generic_to_shared(dA + row * ASTR + c16 * 8);
            asm volatile("cp.async.cg.shared.global [%0], [%1], 16;\n" :: "r"(sa), "l"(g));
        }
        __half* dB = (__half*)(smem + 2 * ASTAGE + s * BSTAGE);
#pragma unroll
        for (int j = 0; j < 2; j++) {   // B: 512 chunks of 16B
            int ci = tid + j * 256;
            int row = ci >> 4, c16 = ci & 15;
            const __half* g = Bw + (size_t)(brow + row) * NG + nblk + c16 * 8;
            uint32_t sb = (uint32_t)__cvta_generic_to_shared(dB + row * BSTR + c16 * 8);
            asm volatile("cp.async.cg.shared.global [%0], [%1], 16;\n" :: "r"(sb), "l"(g));
        }
        asm volatile("cp.async.commit_group;\n");
    };

    loadTile(0, 0);
    for (int kt = 0; kt < KT; kt++) {
        int s = kt & 1;
        asm volatile("cp.async.wait_group 0;\n");
        __syncthreads();
        if (kt + 1 < KT) loadTile(kt + 1, s ^ 1);
        const __half* cA = (const __half*)(smem + s * ASTAGE);
        const __half* cB = (const __half*)(smem + 2 * ASTAGE + s * BSTAGE);
#pragma unroll
        for (int ks = 0; ks < 2; ks++) {
            uint32_t a[2][4], bf[2][4];
#pragma unroll
            for (int mf = 0; mf < 2; mf++) {
                uint32_t ad = (uint32_t)__cvta_generic_to_shared(
                    cA + (wm + mf * 16 + (lane & 15)) * ASTR + ks * 16 + (lane >> 4) * 8);
                asm volatile("ldmatrix.sync.aligned.x4.m8n8.shared.b16 {%0,%1,%2,%3}, [%4];\n"
                             : "=r"(a[mf][0]), "=r"(a[mf][1]), "=r"(a[mf][2]), "=r"(a[mf][3])
                             : "r"(ad));
            }
#pragma unroll
            for (int ng = 0; ng < 2; ng++) {
                uint32_t ad = (uint32_t)__cvta_generic_to_shared(
                    cB + (ks * 16 + ((lane >> 3) & 1) * 8 + (lane & 7)) * BSTR
                       + wn + ng * 16 + (lane >> 4) * 8);
                asm volatile("ldmatrix.sync.aligned.x4.trans.m8n8.shared.b16 {%0,%1,%2,%3}, [%4];\n"
                             : "=r"(bf[ng][0]), "=r"(bf[ng][1]), "=r"(bf[ng][2]), "=r"(bf[ng][3])
                             : "r"(ad));
            }
#pragma unroll
            for (int mf = 0; mf < 2; mf++)
#pragma unroll
                for (int j = 0; j < 4; j++) {
                    uint32_t b0 = bf[j >> 1][(j & 1) * 2], b1 = bf[j >> 1][(j & 1) * 2 + 1];
                    asm volatile(
                        "mma.sync.aligned.m16n8k16.row.col.f32.f16.f16.f32 "
                        "{%0,%1,%2,%3}, {%4,%5,%6,%7}, {%8,%9}, {%0,%1,%2,%3};\n"
                        : "+f"(acc[mf][j][0]), "+f"(acc[mf][j][1]),
                          "+f"(acc[mf][j][2]), "+f"(acc[mf][j][3])
                        : "r"(a[mf][0]), "r"(a[mf][1]), "r"(a[mf][2]), "r"(a[mf][3]),
                          "r"(b0), "r"(b1));
                }
        }
    }

    // ---------------- Epilogue ----------------
    if (epi == 0) {   // raw z -> g_D0h fp16
#pragma unroll
        for (int mf = 0; mf < 2; mf++) {
            int r0 = mblk + wm + mf * 16 + (lane >> 2);
#pragma unroll
            for (int j = 0; j < 4; j++) {
                int n = nblk + wn + j * 8 + (lane & 3) * 2;
                *(__half2*)&g_D0h[(size_t)r0 * NG + n] =
                    __floats2half2_rn(acc[mf][j][0], acc[mf][j][1]);
                *(__half2*)&g_D0h[(size_t)(r0 + 8) * NG + n] =
                    __floats2half2_rn(acc[mf][j][2], acc[mf][j][3]);
            }
        }
        return;
    }

    // LSTM cell: stage via smem for fully-coalesced global I/O.
    float*  cS = (float*)smem;                       // [64][CSTR] floats (9216 B)
    __half* hS = (__half*)(smem + 64 * CSTR * 4);    // [64][HSTR] halfs (9216 B)
    const int u0 = nblk >> 2;                        // unit base (32 units per CTA)

    __syncthreads();
    if (!czero) {
#pragma unroll
        for (int i = tid; i < 512; i += 256) {       // c_old: 64 rows x 32 floats
            int row = i >> 3, c4 = i & 7;
            float4 v = *(const float4*)&g_c[(size_t)(mblk + row) * Hsz + u0 + c4 * 4];
            *(float4*)&cS[row * CSTR + c4 * 4] = v;
        }
    }
    __syncthreads();

    const float* __restrict__ bp = bsel ? g_bias_d : g_bias_e;
    const int odd = lane & 1;
#pragma unroll
    for (int mf = 0; mf < 2; mf++) {
        int r0 = mblk + wm + mf * 16 + (lane >> 2);
#pragma unroll
        for (int j = 0; j < 4; j++) {
            int n = nblk + wn + j * 8 + (lane & 3) * 2;
            float c0 = acc[mf][j][0], c1 = acc[mf][j][1];
            float c2 = acc[mf][j][2], c3 = acc[mf][j][3];
            float2 bb = *(const float2*)&bp[n];
            c0 += bb.x; c1 += bb.y; c2 += bb.x; c3 += bb.y;
            if (epi == 2) {
                float2 dA = __half22float2(*(const __half2*)&g_D0h[(size_t)r0 * NG + n]);
                float2 dB = __half22float2(*(const __half2*)&g_D0h[(size_t)(r0 + 8) * NG + n]);
                c0 += dA.x; c1 += dA.y; c2 += dB.x; c3 += dB.y;
            }
            float p0 = __shfl_xor_sync(0xFFFFFFFFu, c0, 1);
            float p1 = __shfl_xor_sync(0xFFFFFFFFu, c1, 1);
            float p2 = __shfl_xor_sync(0xFFFFFFFFu, c2, 1);
            float p3 = __shfl_xor_sync(0xFFFFFFFFu, c3, 1);
            float gi = odd ? p2 : c0;
            float gf = odd ? p3 : c1;
            float gg = odd ? c2 : p0;
            float go = odd ? c3 : p1;
            int rloc = wm + mf * 16 + (lane >> 2) + (odd ? 8 : 0);
            int uloc = ((wn + j * 8) >> 2) + ((lane >> 1) & 1);
            float i = sigm_(gi), f = sigm_(gf), g = tanh_(gg), o = sigm_(go);
            float cold = czero ? 0.f : cS[rloc * CSTR + uloc];
            float cn = f * cold + i * g;
            float h = o * tanh_(cn);
            cS[rloc * CSTR + uloc] = cn;
            __half hh = __float2half_rn(h);
            hS[rloc * HSTR + uloc] = hh;
            if (epi == 2)
                hS[rloc * HSTR + 32 + uloc] = __float2half_rn(h - __half2float(hh));
        }
    }
    __syncthreads();

    __half* __restrict__ hd = g_h[dstbuf];
#pragma unroll
    for (int i = tid; i < 512; i += 256) {           // c_new: coalesced
        int row = i >> 3, c4 = i & 7;
        float4 v = *(const float4*)&cS[row * CSTR + c4 * 4];
        *(float4*)&g_c[(size_t)(mblk + row) * Hsz + u0 + c4 * 4] = v;
    }
    {
        int i = tid;                                  // h fp16: 256 chunks, 1/thread
        int row = i >> 2, c16 = i & 3;
        uint4 v = *(const uint4*)&hS[row * HSTR + c16 * 8];
        *(uint4*)&hd[(size_t)(mblk + row) * 256 + u0 + c16 * 8] = v;
    }
    if (epi == 2) {
#pragma unroll
        for (int i = tid; i < 512; i += 256) {       // g_dec fp32 (hi+lo)
            int row = i >> 3, c4 = i & 7;
            const __half* hp = &hS[row * HSTR + c4 * 4];
            float4 o;
            o.x = __half2float(hp[0]) + __half2float(hp[32]);
            o.y = __half2float(hp[1]) + __half2float(hp[33]);
            o.z = __half2float(hp[2]) + __half2float(hp[34]);
            o.w = __half2float(hp[3]) + __half2float(hp[35]);
            *(float4*)&g_dec[((size_t)(mblk + row) * Psz + pstep) * Hsz + u0 + c4 * 4] = o;
        }
    }
}

// ---------------------------------------------------------------------------
// Decoder step 0 (h=0 -> z = D0 + bias, no GEMM needed)
// ---------------------------------------------------------------------------
__global__ void k_cell0() {
    int idx = blockIdx.x * blockDim.x + threadIdx.x;   // Bsz*Hsz
    if (idx >= Bsz * Hsz) return;
    int b = idx >> 8, u = idx & 255;
    const __half* zp = &g_D0h[(size_t)b * NG + 4 * u];
    float4 bi = *(const float4*)&g_bias_d[4 * u];
    float i = sigm_(__half2float(zp[0]) + bi.x);
    float g = tanh_(__half2float(zp[2]) + bi.z);
    float o = sigm_(__half2float(zp[3]) + bi.w);
    float cn = i * g;                 // c_old = 0
    g_c[idx] = cn;
    float h = o * tanh_(cn);
    g_h[1][(size_t)b * 256 + u] = __float2half_rn(h);
    g_dec[((size_t)b * Psz + 0) * Hsz + u] = h;
}

// ---------------------------------------------------------------------------
// Output heads
// ---------------------------------------------------------------------------
__global__ void k_heads(const float* __restrict__ mk, const float* __restrict__ mb,
                        const float* __restrict__ lk, const float* __restrict__ lb,
                        float* __restrict__ out) {
    int gw = (blockIdx.x * blockDim.x + threadIdx.x) >> 5;
    int lane = threadIdx.x & 31;
    if (gw >= Bsz * Psz) return;
    const float4* d4 = (const float4*)(g_dec + (size_t)gw * Hsz) + lane * 2;
    float4 va = d4[0], vb = d4[1];
    float dv[8] = {va.x, va.y, va.z, va.w, vb.x, vb.y, vb.z, vb.w};
    float m0 = 0.f, m1 = 0.f, v0 = 0.f, v1 = 0.f;
#pragma unroll
    for (int i = 0; i < 8; i++) {
        int k = lane * 8 + i;
        m0 = fmaf(dv[i], mk[2 * k],     m0);
        m1 = fmaf(dv[i], mk[2 * k + 1], m1);
        v0 = fmaf(dv[i], lk[2 * k],     v0);
        v1 = fmaf(dv[i], lk[2 * k + 1], v1);
    }
#pragma unroll
    for (int off = 16; off; off >>= 1) {
        m0 += __shfl_xor_sync(0xFFFFFFFFu, m0, off);
        m1 += __shfl_xor_sync(0xFFFFFFFFu, m1, off);
        v0 += __shfl_xor_sync(0xFFFFFFFFu, v0, off);
        v1 += __shfl_xor_sync(0xFFFFFFFFu, v1, off);
    }
    if (lane == 0) {
        float4 r = make_float4(m0 + mb[0], m1 + mb[1],
                               fmaxf(v0 + lb[0], 0.f), fmaxf(v1 + lb[1], 0.f));
        *(float4*)&out[(size_t)gw * 4] = r;
    }
}

// ---------------------------------------------------------------------------
// Launch
// ---------------------------------------------------------------------------
extern "C" void kernel_launch(void* const* d_in, const int* in_sizes, int n_in,
                              void* d_out, int out_size) {
    (void)in_sizes; (void)n_in; (void)out_size;
    const float* x      = (const float*)d_in[0];
    const float* w_in_k = (const float*)d_in[1];
    const float* w_in_b = (const float*)d_in[2];
    const float* enc_k  = (const float*)d_in[3];
    const float* enc_rk = (const float*)d_in[4];
    const float* enc_b  = (const float*)d_in[5];
    const float* dec_k  = (const float*)d_in[6];
    const float* dec_rk = (const float*)d_in[7];
    const float* dec_b  = (const float*)d_in[8];
    const float* mean_k = (const float*)d_in[9];
    const float* mean_b = (const float*)d_in[10];
    const float* lv_k   = (const float*)d_in[11];
    const float* lv_b   = (const float*)d_in[12];
    float* out = (float*)d_out;

    const dim3 gg(128, 8), gb(256);
    const int packN = (832 * NG + 2048 + 255) / 256;

    // Launch #1: all packing; #2: inproj; #3..: GEMM steps (ncu -s 5 -> a GEMM)
    k_pack_all<<<packN, 256>>>(enc_k, enc_rk, dec_rk, dec_k, enc_b, dec_b);
    k_inproj<<<(Bsz * Tsz) / 32, 256>>>(x, w_in_k, w_in_b);

    // Encoder step 0 (h=0 -> K=64 over h1 only), writes h buf 1, c from zero
    k_gemm<<<gg, gb>>>(2, 0, 1, 0, 0, 1, 1, -1, 0);
    // Encoder steps 1..19
    for (int t = 1; t < Tsz; t++)
        k_gemm<<<gg, gb>>>(0, 0, 1, t & 1, t, (t + 1) & 1, 0, -1, 0);
    // D0 = enc_h @ dec_k (enc final h in buf 0), raw fp16 store
    k_gemm<<<gg, gb>>>(1, 2, 0, 0, -1, 0, 0, -1, 0);
    // Decoder step 0: pointwise (GEMM is identically zero)
    k_cell0<<<(Bsz * Hsz) / 256, 256>>>();
    // Decoder steps 1..14
    for (int d = 1; d < Psz; d++)
        k_gemm<<<gg, gb>>>(1, 1, 2, d & 1, -1, (d + 1) & 1, 0, d, 1);

    k_heads<<<(Bsz * Psz * 32 + 255) / 256, 256>>>(mean_k, mean_b, lv_k, lv_b, out);
}